// round 1
// baseline (speedup 1.0000x reference)
#include <cuda_runtime.h>
#include <math.h>

#define GN     6
#define NCELL  36
#define HID    128
#define NT     128     // threads per block in pair kernel (one agent i per thread)
#define SEG    16      // j-segments (grid.y) -> 1024 blocks for occupancy
#define TJ     512     // j tile size in smem
#define MAXN   8192
#define BI     16      // rows per block in the linear kernel

// Partial occupancy planes: [seg][cell][i]  (i contiguous -> coalesced)
__device__ float g_part[SEG * NCELL * MAXN];

__global__ __launch_bounds__(NT)
void occ_pair_kernel(const float2* __restrict__ obs, int N) {
    __shared__ float2 tile[TJ];
    __shared__ int    occ[NCELL * NT];   // occ[cell*NT + tid]: bank = tid%32, conflict-free

    const int tid = threadIdx.x;
    const int i   = blockIdx.x * NT + tid;
    const int seg = blockIdx.y;
    const int JS  = (N + SEG - 1) / SEG;
    const int j0  = seg * JS;
    const int j1  = min(j0 + JS, N);

    // Sentinel for invalid i (out of range or NaN coords): rel becomes huge,
    // __float2int_rd saturates, unsigned range check excludes everything.
    float xi = -1e30f, yi = -1e30f;
    if (i < N) {
        float2 p = obs[i];
        if (!isnan(p.x) && !isnan(p.y)) { xi = p.x; yi = p.y; }
    }

    #pragma unroll
    for (int c = 0; c < NCELL; c++) occ[c * NT + tid] = 0;
    __syncthreads();

    for (int jb = j0; jb < j1; jb += TJ) {
        const int nj = min(TJ, j1 - jb);
        for (int t = tid; t < nj; t += NT) {
            float2 p = obs[jb + t];
            // Bad j sentinel has opposite sign from bad-i sentinel so that
            // bad-bad pairs also land far out of range.
            if (isnan(p.x) || isnan(p.y)) { p.x = 1e30f; p.y = 1e30f; }
            tile[t] = p;
        }
        __syncthreads();

        #pragma unroll 8
        for (int jj = 0; jj < nj; jj++) {
            float2 p = tile[jj];              // broadcast LDS.64 (same addr all lanes)
            // Exact XLA parity: dx rounds once (FADD); dx*2 is exact, so
            // FFMA(dx,2,3) == RN(dx*2+3) == reference's (sub -> *2 -> +3).
            float rx = fmaf(p.x - xi, 2.0f, 3.0f);
            float ry = fmaf(p.y - yi, 2.0f, 3.0f);
            int ixc = __float2int_rd(rx);     // floor; NaN-free by sanitization
            int iyc = __float2int_rd(ry);
            if ((unsigned)ixc < (unsigned)GN && (unsigned)iyc < (unsigned)GN) {
                occ[(ixc * GN + iyc) * NT + tid] += 1;
            }
        }
        __syncthreads();
    }

    if (i < N) {
        #pragma unroll
        for (int c = 0; c < NCELL; c++)
            g_part[(seg * NCELL + c) * N + i] = (float)occ[c * NT + tid];
    }
}

__global__ __launch_bounds__(HID)
void occ_gemm_kernel(const float2* __restrict__ obs,
                     const float*  __restrict__ W,
                     const float*  __restrict__ b,
                     float*        __restrict__ out, int N) {
    __shared__ float occ_s[NCELL][BI];
    const int tid = threadIdx.x;           // output feature h
    const int i0  = blockIdx.x * BI;

    // W row for this feature in registers (36 regs)
    float w[NCELL];
    #pragma unroll
    for (int c = 0; c < NCELL; c++) w[c] = W[tid * NCELL + c];
    const float bias = b[tid];

    // Reduce the SEG partial planes for this row tile (coalesced: i contiguous)
    for (int f = tid; f < NCELL * BI; f += HID) {
        const int c  = f / BI;
        const int il = f - c * BI;
        const int i  = i0 + il;
        float s = 0.f;
        if (i < N) {
            #pragma unroll
            for (int sg = 0; sg < SEG; sg++)
                s += g_part[(sg * NCELL + c) * N + i];
        }
        occ_s[c][il] = s;
    }
    __syncthreads();

    #pragma unroll
    for (int il = 0; il < BI; il++) {
        const int i = i0 + il;
        if (i >= N) break;
        float2 p = obs[i];
        float acc = bias;
        // Remove the self-pair (counted at cell 21 iff both coords finite)
        if (!isnan(p.x) && !isnan(p.y)) acc -= w[21];
        #pragma unroll
        for (int c = 0; c < NCELL; c++)
            acc = fmaf(occ_s[c][il], w[c], acc);   // occ_s broadcast across lanes
        out[i * HID + tid] = acc;
    }
}

extern "C" void kernel_launch(void* const* d_in, const int* in_sizes, int n_in,
                              void* d_out, int out_size) {
    const float2* obs = (const float2*)d_in[0];
    const float*  W   = (const float*)d_in[1];
    const float*  b   = (const float*)d_in[2];
    float*        out = (float*)d_out;
    const int N = in_sizes[0] / 2;

    dim3 grid1((N + NT - 1) / NT, SEG);
    occ_pair_kernel<<<grid1, NT>>>(obs, N);
    occ_gemm_kernel<<<(N + BI - 1) / BI, HID>>>(obs, W, b, out, N);
}